// round 15
// baseline (speedup 1.0000x reference)
#include <cuda_runtime.h>
#include <cuda_fp16.h>
#include <math.h>
#include <stdint.h>

#define BB 2
#define SS 2048
#define DD 1024
#define HH 16
#define DH 64
#define FF 4096
#define MM (BB*SS)   // 4096 rows

// ---------------- scratch (device globals; no allocation allowed) ----------
__device__ float  g_x1 [MM*DD];
__device__ __half g_rel[(size_t)BB*HH*SS*SS];   // skewed: W[s][t] = q_s·Er[S-1-s+t]
__device__ float  g_x2 [MM*DD];
__device__ float  g_x3 [MM*DD];

__device__ __half g_x1f[MM*DD];
__device__ __half g_x3f[MM*DD];
__device__ __half g_qf [MM*DD];
__device__ __half g_kf [MM*DD];
__device__ __half g_vf [MM*DD];
__device__ __half g_avf[MM*DD];
__device__ __half g_h1f[(size_t)MM*FF];
__device__ __half g_erf[SS*DH];
__device__ __half g_wq[DD*DD], g_wk[DD*DD], g_wv[DD*DD], g_wo[DD*DD];
__device__ __half g_w1[(size_t)DD*FF], g_w2[(size_t)DD*FF];

// ======================= helpers ============================================
__device__ __forceinline__ uint32_t smem_u32(const void* p) {
    uint32_t a;
    asm("{ .reg .u64 t; cvta.to.shared.u64 t, %1; cvt.u32.u64 %0, t; }"
        : "=r"(a) : "l"(p));
    return a;
}
__device__ __forceinline__ void ldsm4(uint32_t* r, uint32_t addr) {
    asm volatile("ldmatrix.sync.aligned.m8n8.x4.shared.b16 {%0,%1,%2,%3}, [%4];"
        : "=r"(r[0]), "=r"(r[1]), "=r"(r[2]), "=r"(r[3]) : "r"(addr));
}
__device__ __forceinline__ void ldsm4t(uint32_t* r, uint32_t addr) {
    asm volatile("ldmatrix.sync.aligned.m8n8.x4.trans.shared.b16 {%0,%1,%2,%3}, [%4];"
        : "=r"(r[0]), "=r"(r[1]), "=r"(r[2]), "=r"(r[3]) : "r"(addr));
}
__device__ __forceinline__ void mma_f16(float* c, const uint32_t* a, const uint32_t* b) {
    asm volatile("mma.sync.aligned.m16n8k16.row.col.f32.f16.f16.f32 "
        "{%0,%1,%2,%3}, {%4,%5,%6,%7}, {%8,%9}, {%0,%1,%2,%3};"
        : "+f"(c[0]), "+f"(c[1]), "+f"(c[2]), "+f"(c[3])
        : "r"(a[0]), "r"(a[1]), "r"(a[2]), "r"(a[3]), "r"(b[0]), "r"(b[1]));
}
__device__ __forceinline__ uint32_t pack_f16(float x, float y) {
    __half2 h = __floats2half2_rn(x, y);
    return *(uint32_t*)&h;
}

#define RSTR 144
#define ASZ (128 * RSTR)          // 18432 B per 128x64 16-bit array
#define QSZ (64 * RSTR)           // 9216 B per 64x64 16-bit array

// ================== weight transpose + fp16: [K][N] -> [N][K] ===============
__global__ __launch_bounds__(256) void convBT4(
    const float* __restrict__ W0, const float* __restrict__ W1x,
    const float* __restrict__ W2x, const float* __restrict__ W3,
    __half* __restrict__ T0, __half* __restrict__ T1,
    __half* __restrict__ T2, __half* __restrict__ T3, int K, int N)
{
    const float* W = (blockIdx.z == 0) ? W0 : (blockIdx.z == 1) ? W1x
                   : (blockIdx.z == 2) ? W2x : W3;
    __half* T = (blockIdx.z == 0) ? T0 : (blockIdx.z == 1) ? T1
              : (blockIdx.z == 2) ? T2 : T3;
    __shared__ float ts[32][33];
    int n0 = blockIdx.x * 32, k0 = blockIdx.y * 32;
    int tx = threadIdx.x & 31, ty = threadIdx.x >> 5;
    #pragma unroll
    for (int i = 0; i < 4; i++)
        ts[ty + 8*i][tx] = W[(size_t)(k0 + ty + 8*i) * N + n0 + tx];
    __syncthreads();
    #pragma unroll
    for (int i = 0; i < 4; i++) {
        int n = ty + 8*i;
        T[(size_t)(n0 + n) * K + k0 + tx] = __float2half_rn(ts[tx][n]);
    }
}

__global__ __launch_bounds__(256) void convBTf(
    const float* __restrict__ W, __half* __restrict__ T, int K, int N)
{
    __shared__ float ts[32][33];
    int n0 = blockIdx.x * 32, k0 = blockIdx.y * 32;
    int tx = threadIdx.x & 31, ty = threadIdx.x >> 5;
    #pragma unroll
    for (int i = 0; i < 4; i++)
        ts[ty + 8*i][tx] = W[(size_t)(k0 + ty + 8*i) * N + n0 + tx];
    __syncthreads();
    #pragma unroll
    for (int i = 0; i < 4; i++) {
        int n = ty + 8*i;
        T[(size_t)(n0 + n) * K + k0 + tx] = __float2half_rn(ts[tx][n]);
    }
}

// -------- elementwise f16 convert (Er) ---------------------------------------
__global__ __launch_bounds__(256) void convEf(
    const float* __restrict__ X, __half* __restrict__ Xf, int n)
{
    int i = blockIdx.x * 1024 + threadIdx.x * 4;
    if (i >= n) return;
    float4 v = *(const float4*)(X + i);
    *(__half2*)(Xf + i)     = __floats2half2_rn(v.x, v.y);
    *(__half2*)(Xf + i + 2) = __floats2half2_rn(v.z, v.w);
}

// ---------------- LayerNorm: fp32 out + fp16 out ----------------------------
__global__ __launch_bounds__(256) void ln_kernel(
    const float* __restrict__ X, const float* __restrict__ g,
    const float* __restrict__ be, float* __restrict__ Y,
    __half* __restrict__ Yf)
{
    int row = blockIdx.x;
    size_t base = (size_t)row * DD;
    int tid = threadIdx.x;
    float4 v = *(const float4*)(X + base + tid * 4);
    float s = v.x + v.y + v.z + v.w;
    float q = v.x*v.x + v.y*v.y + v.z*v.z + v.w*v.w;

    __shared__ float rs[32], rq[32];
    #pragma unroll
    for (int o = 16; o > 0; o >>= 1) {
        s += __shfl_xor_sync(0xFFFFFFFF, s, o);
        q += __shfl_xor_sync(0xFFFFFFFF, q, o);
    }
    int lane = tid & 31, w = tid >> 5;
    if (lane == 0) { rs[w] = s; rq[w] = q; }
    __syncthreads();
    if (w == 0) {
        s = (lane < 8) ? rs[lane] : 0.f;
        q = (lane < 8) ? rq[lane] : 0.f;
        #pragma unroll
        for (int o = 4; o > 0; o >>= 1) {
            s += __shfl_xor_sync(0xFFFFFFFF, s, o);
            q += __shfl_xor_sync(0xFFFFFFFF, q, o);
        }
        if (lane == 0) { rs[0] = s; rq[0] = q; }
    }
    __syncthreads();
    float mean = rs[0] * (1.f / DD);
    float var  = rq[0] * (1.f / DD) - mean * mean;
    float rstd = rsqrtf(var + 1e-5f);

    float4 gv = *(const float4*)(g  + tid * 4);
    float4 bv = *(const float4*)(be + tid * 4);
    float4 o4;
    o4.x = (v.x - mean) * rstd * gv.x + bv.x;
    o4.y = (v.y - mean) * rstd * gv.y + bv.y;
    o4.z = (v.z - mean) * rstd * gv.z + bv.z;
    o4.w = (v.w - mean) * rstd * gv.w + bv.w;
    *(float4*)(Y + base + tid * 4) = o4;
    *(__half2*)(Yf + base + tid*4)     = __floats2half2_rn(o4.x, o4.y);
    *(__half2*)(Yf + base + tid*4 + 2) = __floats2half2_rn(o4.z, o4.w);
}

// ====== mma.sync fp16 GEMM: C = epi(A@B^T + bias), sync staging =============
#define SA 0
#define SB ASZ
#define GEMM_SMEM (2*ASZ)         // 36864 B

template<int OUTM, bool RELU, bool RES>
__device__ __forceinline__ void gemm_body(
    char* smem, uint32_t sb,
    const __half* __restrict__ Am, const __half* __restrict__ Bm,
    const float* __restrict__ bias, const float* __restrict__ res,
    float* __restrict__ Cf, __half* __restrict__ Cs,
    int N, int K, float scale, int m0, int n0)
{
    int tid = threadIdx.x;
    int lane = tid & 31, wid = tid >> 5;
    int wm = wid & 3, wn = wid >> 2;

    int aRow = wm * 32 + ((lane >> 3) & 1) * 8 + (lane & 7);
    uint32_t aOff = (uint32_t)aRow * RSTR + ((lane >> 4) & 1) * 16;
    int bRow = wn * 64 + ((lane >> 4) & 1) * 8 + (lane & 7);
    uint32_t bOff = (uint32_t)bRow * RSTR + ((lane >> 3) & 1) * 16;

    float acc[2][8][4] = {};

    const int chunks = K >> 6;
    for (int c = 0; c < chunks; c++) {
        size_t koff = (size_t)c * 64;
        #pragma unroll
        for (int i = 0; i < 4; i++) {
            int u = tid + i * 256;
            int row = u >> 3, seg = u & 7;
            uint32_t d = (uint32_t)row * RSTR + seg * 16;
            *(uint4*)(smem + SA + d) = *((const uint4*)(Am + (size_t)(m0+row)*K + koff) + seg);
            *(uint4*)(smem + SB + d) = *((const uint4*)(Bm + (size_t)(n0+row)*K + koff) + seg);
        }
        __syncthreads();

        #pragma unroll
        for (int kk = 0; kk < 4; kk++) {
            uint32_t kb = kk * 32;
            uint32_t ah[2][4];
            ldsm4(ah[0], sb + SA + aOff + kb);
            ldsm4(ah[1], sb + SA + aOff + 16*RSTR + kb);
            uint32_t bh[4][4];
            #pragma unroll
            for (int jp = 0; jp < 4; jp++)
                ldsm4(bh[jp], sb + SB + bOff + (uint32_t)jp*16*RSTR + kb);
            #pragma unroll
            for (int im = 0; im < 2; im++)
                #pragma unroll
                for (int jn = 0; jn < 8; jn++)
                    mma_f16(acc[im][jn], ah[im], &bh[jn >> 1][(jn & 1) * 2]);
        }
        __syncthreads();
    }

    int r = lane >> 2, cc = (lane & 3) * 2;
    #pragma unroll
    for (int im = 0; im < 2; im++) {
        int rg0 = m0 + wm * 32 + im * 16 + r;
        #pragma unroll
        for (int jn = 0; jn < 8; jn++) {
            int col = n0 + wn * 64 + jn * 8 + cc;
            float2 bv = *(const float2*)(bias + col);
            float v0 = (acc[im][jn][0] + bv.x) * scale;
            float v1 = (acc[im][jn][1] + bv.y) * scale;
            float v2 = (acc[im][jn][2] + bv.x) * scale;
            float v3 = (acc[im][jn][3] + bv.y) * scale;
            if (RELU) {
                v0 = fmaxf(v0, 0.f); v1 = fmaxf(v1, 0.f);
                v2 = fmaxf(v2, 0.f); v3 = fmaxf(v3, 0.f);
            }
            size_t o0 = (size_t)rg0 * N + col;
            size_t o1 = (size_t)(rg0 + 8) * N + col;
            if (RES) {
                float2 r0 = *(const float2*)(res + o0);
                float2 r1 = *(const float2*)(res + o1);
                v0 += r0.x; v1 += r0.y; v2 += r1.x; v3 += r1.y;
            }
            if (OUTM == 0) {
                *(float2*)(Cf + o0) = make_float2(v0, v1);
                *(float2*)(Cf + o1) = make_float2(v2, v3);
            } else {
                *(__half2*)(Cs + o0) = __floats2half2_rn(v0, v1);
                *(__half2*)(Cs + o1) = __floats2half2_rn(v2, v3);
            }
        }
    }
}

template<int OUTM, bool RELU, bool RES>
__global__ __launch_bounds__(256)
void gemm_mma(
    const __half* __restrict__ Am, const __half* __restrict__ Bm,
    const float* __restrict__ bias, const float* __restrict__ res,
    float* __restrict__ Cf, __half* __restrict__ Cs,
    int N, int K, float scale)
{
    extern __shared__ char smem[];
    gemm_body<OUTM, RELU, RES>(smem, smem_u32(smem), Am, Bm, bias, res,
                               Cf, Cs, N, K, scale,
                               blockIdx.y * 128, blockIdx.x * 128);
}

// fused QKV: blockIdx.z selects weight/bias/output (sync staging body)
__global__ __launch_bounds__(256)
void qkv_mma(
    const __half* __restrict__ X,
    const __half* __restrict__ Wq, const __half* __restrict__ Wk,
    const __half* __restrict__ Wv,
    const float* __restrict__ bq, const float* __restrict__ bk,
    const float* __restrict__ bv,
    __half* __restrict__ Q, __half* __restrict__ Kk, __half* __restrict__ V)
{
    extern __shared__ char smem[];
    int z = blockIdx.z;
    const __half* B = (z == 0) ? Wq : (z == 1) ? Wk : Wv;
    const float* bi = (z == 0) ? bq : (z == 1) ? bk : bv;
    __half* C       = (z == 0) ? Q  : (z == 1) ? Kk : V;
    float scale     = (z == 0) ? 0.125f : 1.f;
    gemm_body<2, false, false>(smem, smem_u32(smem), X, B, bi, nullptr,
                               nullptr, C, DD, DD, scale,
                               blockIdx.y * 128, blockIdx.x * 128);
}

// ===== rel: W[s][t] = q_s · Er[S-1-s+t], stored PRE-SKEWED (K = 64) =========
// Computes R = q@Er^T on band tiles and scatters into skewed layout.
#define REL_SMEM (2*ASZ)

__global__ __launch_bounds__(256)
void rel_mma(
    const __half* __restrict__ Qf, const __half* __restrict__ Ef,
    __half* __restrict__ out)
{
    int m0 = blockIdx.y * 128, n0 = blockIdx.x * 128;
    if (m0 + n0 + 254 < SS - 1) return;   // tile has no t >= 0 element
    int bh = blockIdx.z;
    int b = bh >> 4, h = bh & 15;

    extern __shared__ char smem[];
    uint32_t sb = smem_u32(smem);
    int tid = threadIdx.x;
    int lane = tid & 31, wid = tid >> 5;
    int wm = wid & 3, wn = wid >> 2;

    const __half* Qp = Qf + ((size_t)b * SS) * DD + h * DH;

    #pragma unroll
    for (int i = 0; i < 4; i++) {
        int u = tid + i * 256;
        int row = u >> 3, seg = u & 7;
        uint32_t d = (uint32_t)row * RSTR + seg * 16;
        *(uint4*)(smem + 0   + d) = *((const uint4*)(Qp + (size_t)(m0+row)*DD) + seg);
        *(uint4*)(smem + ASZ + d) = *((const uint4*)(Ef + (size_t)(n0+row)*DH) + seg);
    }
    __syncthreads();

    int aRow = wm * 32 + ((lane >> 3) & 1) * 8 + (lane & 7);
    uint32_t aOff = (uint32_t)aRow * RSTR + ((lane >> 4) & 1) * 16;
    int bRow = wn * 64 + ((lane >> 4) & 1) * 8 + (lane & 7);
    uint32_t bOff = (uint32_t)bRow * RSTR + ((lane >> 3) & 1) * 16;

    float acc[2][8][4] = {};
    #pragma unroll
    for (int kk = 0; kk < 4; kk++) {
        uint32_t kb = kk * 32;
        uint32_t ah[2][4];
        ldsm4(ah[0], sb + 0 + aOff + kb);
        ldsm4(ah[1], sb + 0 + aOff + 16*RSTR + kb);
        uint32_t bhf[4][4];
        #pragma unroll
        for (int jp = 0; jp < 4; jp++)
            ldsm4(bhf[jp], sb + ASZ + bOff + (uint32_t)jp*16*RSTR + kb);
        #pragma unroll
        for (int im = 0; im < 2; im++)
            #pragma unroll
            for (int jn = 0; jn < 8; jn++)
                mma_f16(acc[im][jn], ah[im], &bhf[jn >> 1][(jn & 1) * 2]);
    }

    // scatter into skewed layout: W[s][t], t = col - (SS-1-s); 0 <= t (<= s auto)
    __half* ob = out + (size_t)bh * SS * SS;
    int r = lane >> 2, cc = (lane & 3) * 2;
    #pragma unroll
    for (int im = 0; im < 2; im++) {
        int rg0 = m0 + wm * 32 + im * 16 + r;
        #pragma unroll
        for (int jn = 0; jn < 8; jn++) {
            int col = n0 + wn * 64 + jn * 8 + cc;
            int t0v = col - (SS - 1 - rg0);          // row rg0
            int t8v = t0v + 8;                        // row rg0+8 (t = col-(SS-1-rg0-8))
            __half* p0 = ob + (size_t)rg0 * SS;
            __half* p8 = ob + (size_t)(rg0 + 8) * SS;
            if (t0v     >= 0) p0[t0v]     = __float2half_rn(acc[im][jn][0]);
            if (t0v + 1 >= 0) p0[t0v + 1] = __float2half_rn(acc[im][jn][1]);
            if (t8v     >= 0) p8[t8v]     = __float2half_rn(acc[im][jn][2]);
            if (t8v + 1 >= 0) p8[t8v + 1] = __float2half_rn(acc[im][jn][3]);
        }
    }
}

// ========== flash attention, fp16 single-product ============================
// CTA: one (b,h) and 64 q-rows, 128 threads (4 warps x 16 rows).
#define FL_Q  0
#define FL_K  QSZ
#define FL_V  (QSZ + ASZ)
#define FL_SMEM (QSZ + 2*ASZ)    // 46080 B

__global__ __launch_bounds__(128)
void flash_mma(
    const __half* __restrict__ Qf, const __half* __restrict__ Kf,
    const __half* __restrict__ Vf, const __half* __restrict__ REL,
    __half* __restrict__ Of)
{
    extern __shared__ char smem[];
    uint32_t sb = smem_u32(smem);
    int tid = threadIdx.x;
    int lane = tid & 31, w = tid >> 5;     // 4 warps
    int s0 = blockIdx.x * 64;
    int bh = blockIdx.y;
    int b = bh >> 4, h = bh & 15;

    const __half* qb = Qf + ((size_t)b * SS) * DD + h * DH;
    const __half* kb = Kf + ((size_t)b * SS) * DD + h * DH;
    const __half* vb = Vf + ((size_t)b * SS) * DD + h * DH;

    // stage Q (64 rows, persistent in smem)
    #pragma unroll
    for (int i = 0; i < 4; i++) {
        int u = tid + i * 128;
        int row = u >> 3, seg = u & 7;
        uint32_t d = (uint32_t)row * RSTR + seg * 16;
        *(uint4*)(smem + FL_Q + d) = *((const uint4*)(qb + (size_t)(s0+row)*DD) + seg);
    }

    int g = lane >> 2, qd = lane & 3;
    int sA = s0 + w * 16 + g;
    int sB = sA + 8;
    const __half* rpA = REL + ((size_t)bh * SS + sA) * SS;   // skewed row: W[sA][t]
    const __half* rpB = REL + ((size_t)bh * SS + sB) * SS;

    uint32_t aOff = (uint32_t)(w*16 + ((lane>>3)&1)*8 + (lane&7)) * RSTR + ((lane>>4)&1)*16;
    uint32_t bOff = (uint32_t)(((lane>>4)&1)*8 + (lane&7)) * RSTR + ((lane>>3)&1)*16;
    uint32_t vKr = ((lane>>3)&1)*8 + (lane&7);
    uint32_t vCb = ((lane>>4)&1)*16;

    const float L2E = 1.44269504f;

    float oacc[8][4] = {};
    float mA = -1e30f, mB = -1e30f, lA = 0.f, lB = 0.f;

    for (int c = 0; c < SS/128; c++) {
        int t0 = c * 128;
        __syncthreads();    // protect K/V smem reuse (and Q store on c==0)
        #pragma unroll
        for (int i = 0; i < 8; i++) {
            int u = tid + i * 128;
            int row = u >> 3, seg = u & 7;
            uint32_t d = (uint32_t)row * RSTR + seg * 16;
            *(uint4*)(smem + FL_K + d) = *((const uint4*)(kb + (size_t)(t0+row)*DD) + seg);
            *(uint4*)(smem + FL_V + d) = *((const uint4*)(vb + (size_t)(t0+row)*DD) + seg);
        }
        __syncthreads();

        // S = q @ k^T (fp16 single), 16 n-tiles of 8 cols
        float sacc[16][4] = {};
        #pragma unroll
        for (int kk = 0; kk < 4; kk++) {
            uint32_t kbo = kk * 32;
            uint32_t ah[4];
            ldsm4(ah, sb + FL_Q + aOff + kbo);
            #pragma unroll
            for (int jp = 0; jp < 8; jp++) {
                uint32_t bhf[4];
                ldsm4(bhf, sb + FL_K + bOff + (uint32_t)jp*16*RSTR + kbo);
                mma_f16(sacc[jp*2],   ah, &bhf[0]);
                mma_f16(sacc[jp*2+1], ah, &bhf[2]);
            }
        }

        // skew add from pre-skewed W: aligned half2 loads (t even)
        if (t0 <= sA) {
            #pragma unroll
            for (int jn = 0; jn < 16; jn++) {
                int t = t0 + jn * 8 + qd * 2;
                if (t + 1 <= sA) {
                    float2 f = __half22float2(__ldg((const __half2*)(rpA + t)));
                    sacc[jn][0] += f.x; sacc[jn][1] += f.y;
                } else if (t <= sA) {
                    sacc[jn][0] += __half2float(__ldg(rpA + t));
                }
            }
        }
        if (t0 <= sB) {
            #pragma unroll
            for (int jn = 0; jn < 16; jn++) {
                int t = t0 + jn * 8 + qd * 2;
                if (t + 1 <= sB) {
                    float2 f = __half22float2(__ldg((const __half2*)(rpB + t)));
                    sacc[jn][2] += f.x; sacc[jn][3] += f.y;
                } else if (t <= sB) {
                    sacc[jn][2] += __half2float(__ldg(rpB + t));
                }
            }
        }

        // online softmax (exp2-based, in-place on sacc)
        float cmA = -1e30f, cmB = -1e30f;
        #pragma unroll
        for (int jn = 0; jn < 16; jn++) {
            cmA = fmaxf(cmA, fmaxf(sacc[jn][0], sacc[jn][1]));
            cmB = fmaxf(cmB, fmaxf(sacc[jn][2], sacc[jn][3]));
        }
        cmA = fmaxf(cmA, __shfl_xor_sync(0xFFFFFFFF, cmA, 1));
        cmA = fmaxf(cmA, __shfl_xor_sync(0xFFFFFFFF, cmA, 2));
        cmB = fmaxf(cmB, __shfl_xor_sync(0xFFFFFFFF, cmB, 1));
        cmB = fmaxf(cmB, __shfl_xor_sync(0xFFFFFFFF, cmB, 2));
        float mnA = fmaxf(mA, cmA), mnB = fmaxf(mB, cmB);
        float bA = mnA * L2E, bB = mnB * L2E;
        float alA = exp2f(mA * L2E - bA), alB = exp2f(mB * L2E - bB);
        mA = mnA; mB = mnB;

        float suA = 0.f, suB = 0.f;
        #pragma unroll
        for (int jn = 0; jn < 16; jn++) {
            sacc[jn][0] = exp2f(fmaf(sacc[jn][0], L2E, -bA));
            sacc[jn][1] = exp2f(fmaf(sacc[jn][1], L2E, -bA));
            sacc[jn][2] = exp2f(fmaf(sacc[jn][2], L2E, -bB));
            sacc[jn][3] = exp2f(fmaf(sacc[jn][3], L2E, -bB));
            suA += sacc[jn][0] + sacc[jn][1];
            suB += sacc[jn][2] + sacc[jn][3];
        }
        suA += __shfl_xor_sync(0xFFFFFFFF, suA, 1);
        suA += __shfl_xor_sync(0xFFFFFFFF, suA, 2);
        suB += __shfl_xor_sync(0xFFFFFFFF, suB, 1);
        suB += __shfl_xor_sync(0xFFFFFFFF, suB, 2);
        lA = lA * alA + suA;
        lB = lB * alB + suB;

        // rescale O
        #pragma unroll
        for (int jn = 0; jn < 8; jn++) {
            oacc[jn][0] *= alA; oacc[jn][1] *= alA;
            oacc[jn][2] *= alB; oacc[jn][3] *= alB;
        }

        // O += P @ V (fp16 single), 8 k-steps of 16
        #pragma unroll
        for (int k2 = 0; k2 < 8; k2++) {
            uint32_t pa[4];
            pa[0] = pack_f16(sacc[2*k2][0],   sacc[2*k2][1]);
            pa[1] = pack_f16(sacc[2*k2][2],   sacc[2*k2][3]);
            pa[2] = pack_f16(sacc[2*k2+1][0], sacc[2*k2+1][1]);
            pa[3] = pack_f16(sacc[2*k2+1][2], sacc[2*k2+1][3]);
            uint32_t vRowOff = (uint32_t)(k2 * 16 + vKr) * RSTR;
            #pragma unroll
            for (int jp = 0; jp < 4; jp++) {
                uint32_t vh4[4];
                ldsm4t(vh4, sb + FL_V + vRowOff + vCb + jp * 32);
                mma_f16(oacc[jp*2],   pa, &vh4[0]);
                mma_f16(oacc[jp*2+1], pa, &vh4[2]);
            }
        }
    }

    // epilogue: normalize + fp16 store (for Wo GEMM)
    float invA = 1.f / lA, invB = 1.f / lB;
    #pragma unroll
    for (int jn = 0; jn < 8; jn++) {
        int col = h * DH + jn * 8 + qd * 2;
        size_t oA = ((size_t)b * SS + sA) * DD + col;
        size_t oB = ((size_t)b * SS + sB) * DD + col;
        *(__half2*)(Of + oA) = __floats2half2_rn(oacc[jn][0] * invA, oacc[jn][1] * invA);
        *(__half2*)(Of + oB) = __floats2half2_rn(oacc[jn][2] * invB, oacc[jn][3] * invB);
    }
}

// ---------------- launch ----------------------------------------------------
extern "C" void kernel_launch(void* const* d_in, const int* in_sizes, int n_in,
                              void* d_out, int out_size)
{
    (void)in_sizes; (void)n_in; (void)out_size;
    const float* x   = (const float*)d_in[0];
    const float* Wq  = (const float*)d_in[1];
    const float* bq  = (const float*)d_in[2];
    const float* Wk  = (const float*)d_in[3];
    const float* bk  = (const float*)d_in[4];
    const float* Wv  = (const float*)d_in[5];
    const float* bv  = (const float*)d_in[6];
    const float* Wo  = (const float*)d_in[7];
    const float* bo  = (const float*)d_in[8];
    const float* Er  = (const float*)d_in[9];
    const float* W1  = (const float*)d_in[10];
    const float* b1  = (const float*)d_in[11];
    const float* W2  = (const float*)d_in[12];
    const float* b2  = (const float*)d_in[13];
    const float* g1  = (const float*)d_in[14];
    const float* be1 = (const float*)d_in[15];
    const float* g2  = (const float*)d_in[16];
    const float* be2 = (const float*)d_in[17];
    float* y = (float*)d_out;

    float *px1, *px2, *px3;
    __half *prel;
    cudaGetSymbolAddress((void**)&px1,  g_x1);
    cudaGetSymbolAddress((void**)&prel, g_rel);
    cudaGetSymbolAddress((void**)&px2,  g_x2);
    cudaGetSymbolAddress((void**)&px3,  g_x3);

    __half *x1f,*x3f,*avf,*h1f;
    __half *qf,*kf,*vf,*erf,*wq,*wk,*wv,*wo,*w1,*w2;
    cudaGetSymbolAddress((void**)&x1f, g_x1f);
    cudaGetSymbolAddress((void**)&x3f, g_x3f);
    cudaGetSymbolAddress((void**)&qf,  g_qf);
    cudaGetSymbolAddress((void**)&kf,  g_kf);
    cudaGetSymbolAddress((void**)&vf,  g_vf);
    cudaGetSymbolAddress((void**)&avf, g_avf);
    cudaGetSymbolAddress((void**)&h1f, g_h1f);
    cudaGetSymbolAddress((void**)&erf, g_erf);
    cudaGetSymbolAddress((void**)&wq, g_wq); cudaGetSymbolAddress((void**)&wk, g_wk);
    cudaGetSymbolAddress((void**)&wv, g_wv); cudaGetSymbolAddress((void**)&wo, g_wo);
    cudaGetSymbolAddress((void**)&w1, g_w1); cudaGetSymbolAddress((void**)&w2, g_w2);

    cudaFuncSetAttribute(gemm_mma<0,false,true>,  cudaFuncAttributeMaxDynamicSharedMemorySize, GEMM_SMEM);
    cudaFuncSetAttribute(gemm_mma<2,true,false>,  cudaFuncAttributeMaxDynamicSharedMemorySize, GEMM_SMEM);
    cudaFuncSetAttribute(qkv_mma, cudaFuncAttributeMaxDynamicSharedMemorySize, GEMM_SMEM);
    cudaFuncSetAttribute(rel_mma,   cudaFuncAttributeMaxDynamicSharedMemorySize, REL_SMEM);
    cudaFuncSetAttribute(flash_mma, cudaFuncAttributeMaxDynamicSharedMemorySize, FL_SMEM);

    // weight transpose + fp16 convert (4 DxD batched, 2 big separate)
    convBT4<<<dim3(DD/32, DD/32, 4), 256>>>(Wq, Wk, Wv, Wo, wq, wk, wv, wo, DD, DD);
    convBTf<<<dim3(FF/32, DD/32), 256>>>(W1, w1, DD, FF);
    convBTf<<<dim3(DD/32, FF/32), 256>>>(W2, w2, FF, DD);
    convEf<<<(SS*DH + 1023)/1024, 256>>>(Er, erf, SS*DH);

    // x1 = LN(x)
    ln_kernel<<<MM, 256>>>(x, g1, be1, px1, x1f);
    // q/k/v fused (z selects), synchronous staging body
    qkv_mma<<<dim3(DD/128, MM/128, 3), 256, GEMM_SMEM>>>(
        x1f, wq, wk, wv, bq, bk, bv, qf, kf, vf);
    // rel: skewed W[s][t] (band tiles, fp16)
    rel_mma<<<dim3(SS/128, SS/128, BB*HH), 256, REL_SMEM>>>(qf, erf, prel);
    // fused attention
    flash_mma<<<dim3(SS/64, BB*HH), 128, FL_SMEM>>>(qf, kf, vf, prel, avf);
    // x2 = x1 + av@Wo + bo
    gemm_mma<0,false,true><<<dim3(DD/128, MM/128), 256, GEMM_SMEM>>>(
        avf, wo, bo, px1, px2, nullptr, DD, DD, 1.f);
    // x3 = LN(x2)
    ln_kernel<<<MM, 256>>>(px2, g2, be2, px3, x3f);
    // h1 = relu(x3@W1+b1) -> fp16
    gemm_mma<2,true,false><<<dim3(FF/128, MM/128), 256, GEMM_SMEM>>>(
        x3f, w1, b1, nullptr, nullptr, h1f, FF, DD, 1.f);
    // y = x3 + h1@W2 + b2
    gemm_mma<0,false,true><<<dim3(DD/128, MM/128), 256, GEMM_SMEM>>>(
        h1f, w2, b2, px3, y, nullptr, DD, FF, 1.f);
}

// round 16
// speedup vs baseline: 1.1884x; 1.1884x over previous
#include <cuda_runtime.h>
#include <cuda_fp16.h>
#include <math.h>
#include <stdint.h>

#define BB 2
#define SS 2048
#define DD 1024
#define HH 16
#define DH 64
#define FF 4096
#define MM (BB*SS)   // 4096 rows

// ---------------- scratch (device globals; no allocation allowed) ----------
__device__ float  g_x1 [MM*DD];
__device__ __half g_rel[(size_t)BB*HH*SS*SS];   // q@Er^T band, fp16
__device__ float  g_x2 [MM*DD];
__device__ float  g_x3 [MM*DD];

__device__ __half g_x1f[MM*DD];
__device__ __half g_x3f[MM*DD];
__device__ __half g_qf [MM*DD];
__device__ __half g_kf [MM*DD];
__device__ __half g_vf [MM*DD];
__device__ __half g_avf[MM*DD];
__device__ __half g_h1f[(size_t)MM*FF];
__device__ __half g_erf[SS*DH];
__device__ __half g_wq[DD*DD], g_wk[DD*DD], g_wv[DD*DD], g_wo[DD*DD];
__device__ __half g_w1[(size_t)DD*FF], g_w2[(size_t)DD*FF];

// ======================= helpers ============================================
__device__ __forceinline__ uint32_t smem_u32(const void* p) {
    uint32_t a;
    asm("{ .reg .u64 t; cvta.to.shared.u64 t, %1; cvt.u32.u64 %0, t; }"
        : "=r"(a) : "l"(p));
    return a;
}
__device__ __forceinline__ void ldsm4(uint32_t* r, uint32_t addr) {
    asm volatile("ldmatrix.sync.aligned.m8n8.x4.shared.b16 {%0,%1,%2,%3}, [%4];"
        : "=r"(r[0]), "=r"(r[1]), "=r"(r[2]), "=r"(r[3]) : "r"(addr));
}
__device__ __forceinline__ void ldsm4t(uint32_t* r, uint32_t addr) {
    asm volatile("ldmatrix.sync.aligned.m8n8.x4.trans.shared.b16 {%0,%1,%2,%3}, [%4];"
        : "=r"(r[0]), "=r"(r[1]), "=r"(r[2]), "=r"(r[3]) : "r"(addr));
}
__device__ __forceinline__ void mma_f16(float* c, const uint32_t* a, const uint32_t* b) {
    asm volatile("mma.sync.aligned.m16n8k16.row.col.f32.f16.f16.f32 "
        "{%0,%1,%2,%3}, {%4,%5,%6,%7}, {%8,%9}, {%0,%1,%2,%3};"
        : "+f"(c[0]), "+f"(c[1]), "+f"(c[2]), "+f"(c[3])
        : "r"(a[0]), "r"(a[1]), "r"(a[2]), "r"(a[3]), "r"(b[0]), "r"(b[1]));
}
__device__ __forceinline__ uint32_t pack_f16(float x, float y) {
    __half2 h = __floats2half2_rn(x, y);
    return *(uint32_t*)&h;
}

#define RSTR 144
#define ASZ (128 * RSTR)          // 18432 B per 128x64 16-bit array
#define QSZ (64 * RSTR)           // 9216 B per 64x64 16-bit array

// ================== weight transpose + fp16: [K][N] -> [N][K] ===============
__global__ __launch_bounds__(256) void convBT4(
    const float* __restrict__ W0, const float* __restrict__ W1x,
    const float* __restrict__ W2x, const float* __restrict__ W3,
    __half* __restrict__ T0, __half* __restrict__ T1,
    __half* __restrict__ T2, __half* __restrict__ T3, int K, int N)
{
    const float* W = (blockIdx.z == 0) ? W0 : (blockIdx.z == 1) ? W1x
                   : (blockIdx.z == 2) ? W2x : W3;
    __half* T = (blockIdx.z == 0) ? T0 : (blockIdx.z == 1) ? T1
              : (blockIdx.z == 2) ? T2 : T3;
    __shared__ float ts[32][33];
    int n0 = blockIdx.x * 32, k0 = blockIdx.y * 32;
    int tx = threadIdx.x & 31, ty = threadIdx.x >> 5;
    #pragma unroll
    for (int i = 0; i < 4; i++)
        ts[ty + 8*i][tx] = W[(size_t)(k0 + ty + 8*i) * N + n0 + tx];
    __syncthreads();
    #pragma unroll
    for (int i = 0; i < 4; i++) {
        int n = ty + 8*i;
        T[(size_t)(n0 + n) * K + k0 + tx] = __float2half_rn(ts[tx][n]);
    }
}

__global__ __launch_bounds__(256) void convBTf(
    const float* __restrict__ W, __half* __restrict__ T, int K, int N)
{
    __shared__ float ts[32][33];
    int n0 = blockIdx.x * 32, k0 = blockIdx.y * 32;
    int tx = threadIdx.x & 31, ty = threadIdx.x >> 5;
    #pragma unroll
    for (int i = 0; i < 4; i++)
        ts[ty + 8*i][tx] = W[(size_t)(k0 + ty + 8*i) * N + n0 + tx];
    __syncthreads();
    #pragma unroll
    for (int i = 0; i < 4; i++) {
        int n = ty + 8*i;
        T[(size_t)(n0 + n) * K + k0 + tx] = __float2half_rn(ts[tx][n]);
    }
}

// -------- elementwise f16 convert (Er) ---------------------------------------
__global__ __launch_bounds__(256) void convEf(
    const float* __restrict__ X, __half* __restrict__ Xf, int n)
{
    int i = blockIdx.x * 1024 + threadIdx.x * 4;
    if (i >= n) return;
    float4 v = *(const float4*)(X + i);
    *(__half2*)(Xf + i)     = __floats2half2_rn(v.x, v.y);
    *(__half2*)(Xf + i + 2) = __floats2half2_rn(v.z, v.w);
}

// ---------------- LayerNorm: fp32 out + fp16 out ----------------------------
__global__ __launch_bounds__(256) void ln_kernel(
    const float* __restrict__ X, const float* __restrict__ g,
    const float* __restrict__ be, float* __restrict__ Y,
    __half* __restrict__ Yf)
{
    int row = blockIdx.x;
    size_t base = (size_t)row * DD;
    int tid = threadIdx.x;
    float4 v = *(const float4*)(X + base + tid * 4);
    float s = v.x + v.y + v.z + v.w;
    float q = v.x*v.x + v.y*v.y + v.z*v.z + v.w*v.w;

    __shared__ float rs[32], rq[32];
    #pragma unroll
    for (int o = 16; o > 0; o >>= 1) {
        s += __shfl_xor_sync(0xFFFFFFFF, s, o);
        q += __shfl_xor_sync(0xFFFFFFFF, q, o);
    }
    int lane = tid & 31, w = tid >> 5;
    if (lane == 0) { rs[w] = s; rq[w] = q; }
    __syncthreads();
    if (w == 0) {
        s = (lane < 8) ? rs[lane] : 0.f;
        q = (lane < 8) ? rq[lane] : 0.f;
        #pragma unroll
        for (int o = 4; o > 0; o >>= 1) {
            s += __shfl_xor_sync(0xFFFFFFFF, s, o);
            q += __shfl_xor_sync(0xFFFFFFFF, q, o);
        }
        if (lane == 0) { rs[0] = s; rq[0] = q; }
    }
    __syncthreads();
    float mean = rs[0] * (1.f / DD);
    float var  = rq[0] * (1.f / DD) - mean * mean;
    float rstd = rsqrtf(var + 1e-5f);

    float4 gv = *(const float4*)(g  + tid * 4);
    float4 bv = *(const float4*)(be + tid * 4);
    float4 o4;
    o4.x = (v.x - mean) * rstd * gv.x + bv.x;
    o4.y = (v.y - mean) * rstd * gv.y + bv.y;
    o4.z = (v.z - mean) * rstd * gv.z + bv.z;
    o4.w = (v.w - mean) * rstd * gv.w + bv.w;
    *(float4*)(Y + base + tid * 4) = o4;
    *(__half2*)(Yf + base + tid*4)     = __floats2half2_rn(o4.x, o4.y);
    *(__half2*)(Yf + base + tid*4 + 2) = __floats2half2_rn(o4.z, o4.w);
}

// ====== mma.sync fp16 GEMM: C = epi(A@B^T + bias), sync staging =============
#define SA 0
#define SB ASZ
#define GEMM_SMEM (2*ASZ)         // 36864 B

template<int OUTM, bool RELU, bool RES>
__device__ __forceinline__ void gemm_body(
    char* smem, uint32_t sb,
    const __half* __restrict__ Am, const __half* __restrict__ Bm,
    const float* __restrict__ bias, const float* __restrict__ res,
    float* __restrict__ Cf, __half* __restrict__ Cs,
    int N, int K, float scale, int m0, int n0)
{
    int tid = threadIdx.x;
    int lane = tid & 31, wid = tid >> 5;
    int wm = wid & 3, wn = wid >> 2;

    int aRow = wm * 32 + ((lane >> 3) & 1) * 8 + (lane & 7);
    uint32_t aOff = (uint32_t)aRow * RSTR + ((lane >> 4) & 1) * 16;
    int bRow = wn * 64 + ((lane >> 4) & 1) * 8 + (lane & 7);
    uint32_t bOff = (uint32_t)bRow * RSTR + ((lane >> 3) & 1) * 16;

    float acc[2][8][4] = {};

    const int chunks = K >> 6;
    for (int c = 0; c < chunks; c++) {
        size_t koff = (size_t)c * 64;
        #pragma unroll
        for (int i = 0; i < 4; i++) {
            int u = tid + i * 256;
            int row = u >> 3, seg = u & 7;
            uint32_t d = (uint32_t)row * RSTR + seg * 16;
            *(uint4*)(smem + SA + d) = *((const uint4*)(Am + (size_t)(m0+row)*K + koff) + seg);
            *(uint4*)(smem + SB + d) = *((const uint4*)(Bm + (size_t)(n0+row)*K + koff) + seg);
        }
        __syncthreads();

        #pragma unroll
        for (int kk = 0; kk < 4; kk++) {
            uint32_t kb = kk * 32;
            uint32_t ah[2][4];
            ldsm4(ah[0], sb + SA + aOff + kb);
            ldsm4(ah[1], sb + SA + aOff + 16*RSTR + kb);
            uint32_t bh[4][4];
            #pragma unroll
            for (int jp = 0; jp < 4; jp++)
                ldsm4(bh[jp], sb + SB + bOff + (uint32_t)jp*16*RSTR + kb);
            #pragma unroll
            for (int im = 0; im < 2; im++)
                #pragma unroll
                for (int jn = 0; jn < 8; jn++)
                    mma_f16(acc[im][jn], ah[im], &bh[jn >> 1][(jn & 1) * 2]);
        }
        __syncthreads();
    }

    int r = lane >> 2, cc = (lane & 3) * 2;
    #pragma unroll
    for (int im = 0; im < 2; im++) {
        int rg0 = m0 + wm * 32 + im * 16 + r;
        #pragma unroll
        for (int jn = 0; jn < 8; jn++) {
            int col = n0 + wn * 64 + jn * 8 + cc;
            float2 bv = *(const float2*)(bias + col);
            float v0 = (acc[im][jn][0] + bv.x) * scale;
            float v1 = (acc[im][jn][1] + bv.y) * scale;
            float v2 = (acc[im][jn][2] + bv.x) * scale;
            float v3 = (acc[im][jn][3] + bv.y) * scale;
            if (RELU) {
                v0 = fmaxf(v0, 0.f); v1 = fmaxf(v1, 0.f);
                v2 = fmaxf(v2, 0.f); v3 = fmaxf(v3, 0.f);
            }
            size_t o0 = (size_t)rg0 * N + col;
            size_t o1 = (size_t)(rg0 + 8) * N + col;
            if (RES) {
                float2 r0 = *(const float2*)(res + o0);
                float2 r1 = *(const float2*)(res + o1);
                v0 += r0.x; v1 += r0.y; v2 += r1.x; v3 += r1.y;
            }
            if (OUTM == 0) {
                *(float2*)(Cf + o0) = make_float2(v0, v1);
                *(float2*)(Cf + o1) = make_float2(v2, v3);
            } else {
                *(__half2*)(Cs + o0) = __floats2half2_rn(v0, v1);
                *(__half2*)(Cs + o1) = __floats2half2_rn(v2, v3);
            }
        }
    }
}

template<int OUTM, bool RELU, bool RES>
__global__ __launch_bounds__(256)
void gemm_mma(
    const __half* __restrict__ Am, const __half* __restrict__ Bm,
    const float* __restrict__ bias, const float* __restrict__ res,
    float* __restrict__ Cf, __half* __restrict__ Cs,
    int N, int K, float scale)
{
    extern __shared__ char smem[];
    gemm_body<OUTM, RELU, RES>(smem, smem_u32(smem), Am, Bm, bias, res,
                               Cf, Cs, N, K, scale,
                               blockIdx.y * 128, blockIdx.x * 128);
}

// fused QKV: blockIdx.z selects weight/bias/output (sync staging body)
__global__ __launch_bounds__(256)
void qkv_mma(
    const __half* __restrict__ X,
    const __half* __restrict__ Wq, const __half* __restrict__ Wk,
    const __half* __restrict__ Wv,
    const float* __restrict__ bq, const float* __restrict__ bk,
    const float* __restrict__ bv,
    __half* __restrict__ Q, __half* __restrict__ Kk, __half* __restrict__ V)
{
    extern __shared__ char smem[];
    int z = blockIdx.z;
    const __half* B = (z == 0) ? Wq : (z == 1) ? Wk : Wv;
    const float* bi = (z == 0) ? bq : (z == 1) ? bk : bv;
    __half* C       = (z == 0) ? Q  : (z == 1) ? Kk : V;
    float scale     = (z == 0) ? 0.125f : 1.f;
    gemm_body<2, false, false>(smem, smem_u32(smem), X, B, bi, nullptr,
                               nullptr, C, DD, DD, scale,
                               blockIdx.y * 128, blockIdx.x * 128);
}

// ========== rel = q @ Er^T, band tiles only, fp16 in/out (K = 64) ===========
#define REL_SMEM (2*ASZ)

__global__ __launch_bounds__(256)
void rel_mma(
    const __half* __restrict__ Qf, const __half* __restrict__ Ef,
    __half* __restrict__ out)
{
    int m0 = blockIdx.y * 128, n0 = blockIdx.x * 128;
    if (m0 + n0 + 255 < SS - 1) return;   // tile never read by skew gather
    int bh = blockIdx.z;
    int b = bh >> 4, h = bh & 15;

    extern __shared__ char smem[];
    uint32_t sb = smem_u32(smem);
    int tid = threadIdx.x;
    int lane = tid & 31, wid = tid >> 5;
    int wm = wid & 3, wn = wid >> 2;

    const __half* Qp = Qf + ((size_t)b * SS) * DD + h * DH;

    #pragma unroll
    for (int i = 0; i < 4; i++) {
        int u = tid + i * 256;
        int row = u >> 3, seg = u & 7;
        uint32_t d = (uint32_t)row * RSTR + seg * 16;
        *(uint4*)(smem + 0   + d) = *((const uint4*)(Qp + (size_t)(m0+row)*DD) + seg);
        *(uint4*)(smem + ASZ + d) = *((const uint4*)(Ef + (size_t)(n0+row)*DH) + seg);
    }
    __syncthreads();

    int aRow = wm * 32 + ((lane >> 3) & 1) * 8 + (lane & 7);
    uint32_t aOff = (uint32_t)aRow * RSTR + ((lane >> 4) & 1) * 16;
    int bRow = wn * 64 + ((lane >> 4) & 1) * 8 + (lane & 7);
    uint32_t bOff = (uint32_t)bRow * RSTR + ((lane >> 3) & 1) * 16;

    float acc[2][8][4] = {};
    #pragma unroll
    for (int kk = 0; kk < 4; kk++) {
        uint32_t kb = kk * 32;
        uint32_t ah[2][4];
        ldsm4(ah[0], sb + 0 + aOff + kb);
        ldsm4(ah[1], sb + 0 + aOff + 16*RSTR + kb);
        uint32_t bhf[4][4];
        #pragma unroll
        for (int jp = 0; jp < 4; jp++)
            ldsm4(bhf[jp], sb + ASZ + bOff + (uint32_t)jp*16*RSTR + kb);
        #pragma unroll
        for (int im = 0; im < 2; im++)
            #pragma unroll
            for (int jn = 0; jn < 8; jn++)
                mma_f16(acc[im][jn], ah[im], &bhf[jn >> 1][(jn & 1) * 2]);
    }

    __half* ob = out + (size_t)bh * SS * SS;
    int r = lane >> 2, cc = (lane & 3) * 2;
    #pragma unroll
    for (int im = 0; im < 2; im++) {
        int rg0 = m0 + wm * 32 + im * 16 + r;
        #pragma unroll
        for (int jn = 0; jn < 8; jn++) {
            int col = n0 + wn * 64 + jn * 8 + cc;
            *(__half2*)(ob + (size_t)rg0 * SS + col)     = __floats2half2_rn(acc[im][jn][0], acc[im][jn][1]);
            *(__half2*)(ob + (size_t)(rg0+8) * SS + col) = __floats2half2_rn(acc[im][jn][2], acc[im][jn][3]);
        }
    }
}

// ========== flash attention, fp16 single-product ============================
// CTA: one (b,h) and 64 q-rows, 128 threads (4 warps x 16 rows).
#define FL_Q  0
#define FL_K  QSZ
#define FL_V  (QSZ + ASZ)
#define FL_SMEM (QSZ + 2*ASZ)    // 46080 B

__global__ __launch_bounds__(128)
void flash_mma(
    const __half* __restrict__ Qf, const __half* __restrict__ Kf,
    const __half* __restrict__ Vf, const __half* __restrict__ REL,
    __half* __restrict__ Of)
{
    extern __shared__ char smem[];
    uint32_t sb = smem_u32(smem);
    int tid = threadIdx.x;
    int lane = tid & 31, w = tid >> 5;     // 4 warps
    int s0 = blockIdx.x * 64;
    int bh = blockIdx.y;
    int b = bh >> 4, h = bh & 15;

    const __half* qb = Qf + ((size_t)b * SS) * DD + h * DH;
    const __half* kb = Kf + ((size_t)b * SS) * DD + h * DH;
    const __half* vb = Vf + ((size_t)b * SS) * DD + h * DH;

    // stage Q (64 rows, persistent in smem)
    #pragma unroll
    for (int i = 0; i < 4; i++) {
        int u = tid + i * 128;
        int row = u >> 3, seg = u & 7;
        uint32_t d = (uint32_t)row * RSTR + seg * 16;
        *(uint4*)(smem + FL_Q + d) = *((const uint4*)(qb + (size_t)(s0+row)*DD) + seg);
    }

    int g = lane >> 2, qd = lane & 3;
    int sA = s0 + w * 16 + g;
    int sB = sA + 8;
    const __half* rpA = REL + ((size_t)bh * SS + sA) * SS + (SS - 1 - sA);
    const __half* rpB = REL + ((size_t)bh * SS + sB) * SS + (SS - 1 - sB);

    uint32_t aOff = (uint32_t)(w*16 + ((lane>>3)&1)*8 + (lane&7)) * RSTR + ((lane>>4)&1)*16;
    uint32_t bOff = (uint32_t)(((lane>>4)&1)*8 + (lane&7)) * RSTR + ((lane>>3)&1)*16;
    uint32_t vKr = ((lane>>3)&1)*8 + (lane&7);
    uint32_t vCb = ((lane>>4)&1)*16;

    const float L2E = 1.44269504f;

    float oacc[8][4] = {};
    float mA = -1e30f, mB = -1e30f, lA = 0.f, lB = 0.f;

    for (int c = 0; c < SS/128; c++) {
        int t0 = c * 128;
        __syncthreads();    // protect K/V smem reuse (and Q store on c==0)
        #pragma unroll
        for (int i = 0; i < 8; i++) {
            int u = tid + i * 128;
            int row = u >> 3, seg = u & 7;
            uint32_t d = (uint32_t)row * RSTR + seg * 16;
            *(uint4*)(smem + FL_K + d) = *((const uint4*)(kb + (size_t)(t0+row)*DD) + seg);
            *(uint4*)(smem + FL_V + d) = *((const uint4*)(vb + (size_t)(t0+row)*DD) + seg);
        }
        __syncthreads();

        // S = q @ k^T (fp16 single), 16 n-tiles of 8 cols
        float sacc[16][4] = {};
        #pragma unroll
        for (int kk = 0; kk < 4; kk++) {
            uint32_t kbo = kk * 32;
            uint32_t ah[4];
            ldsm4(ah, sb + FL_Q + aOff + kbo);
            #pragma unroll
            for (int jp = 0; jp < 8; jp++) {
                uint32_t bhf[4];
                ldsm4(bhf, sb + FL_K + bOff + (uint32_t)jp*16*RSTR + kbo);
                mma_f16(sacc[jp*2],   ah, &bhf[0]);
                mma_f16(sacc[jp*2+1], ah, &bhf[2]);
            }
        }

        // skew add (fp16 rel): sacc[jn][0,1] row sA, [2,3] row sB
        if (t0 <= sA) {
            #pragma unroll
            for (int jn = 0; jn < 16; jn++) {
                int t = t0 + jn * 8 + qd * 2;
                if (t     <= sA) sacc[jn][0] += __half2float(__ldg(rpA + t));
                if (t + 1 <= sA) sacc[jn][1] += __half2float(__ldg(rpA + t + 1));
            }
        }
        if (t0 <= sB) {
            #pragma unroll
            for (int jn = 0; jn < 16; jn++) {
                int t = t0 + jn * 8 + qd * 2;
                if (t     <= sB) sacc[jn][2] += __half2float(__ldg(rpB + t));
                if (t + 1 <= sB) sacc[jn][3] += __half2float(__ldg(rpB + t + 1));
            }
        }

        // online softmax (exp2-based, in-place on sacc)
        float cmA = -1e30f, cmB = -1e30f;
        #pragma unroll
        for (int jn = 0; jn < 16; jn++) {
            cmA = fmaxf(cmA, fmaxf(sacc[jn][0], sacc[jn][1]));
            cmB = fmaxf(cmB, fmaxf(sacc[jn][2], sacc[jn][3]));
        }
        cmA = fmaxf(cmA, __shfl_xor_sync(0xFFFFFFFF, cmA, 1));
        cmA = fmaxf(cmA, __shfl_xor_sync(0xFFFFFFFF, cmA, 2));
        cmB = fmaxf(cmB, __shfl_xor_sync(0xFFFFFFFF, cmB, 1));
        cmB = fmaxf(cmB, __shfl_xor_sync(0xFFFFFFFF, cmB, 2));
        float mnA = fmaxf(mA, cmA), mnB = fmaxf(mB, cmB);
        float bA = mnA * L2E, bB = mnB * L2E;
        float alA = exp2f(mA * L2E - bA), alB = exp2f(mB * L2E - bB);
        mA = mnA; mB = mnB;

        float suA = 0.f, suB = 0.f;
        #pragma unroll
        for (int jn = 0; jn < 16; jn++) {
            sacc[jn][0] = exp2f(fmaf(sacc[jn][0], L2E, -bA));
            sacc[jn][1] = exp2f(fmaf(sacc[jn][1], L2E, -bA));
            sacc[jn][2] = exp2f(fmaf(sacc[jn][2], L2E, -bB));
            sacc[jn][3] = exp2f(fmaf(sacc[jn][3], L2E, -bB));
            suA += sacc[jn][0] + sacc[jn][1];
            suB += sacc[jn][2] + sacc[jn][3];
        }
        suA += __shfl_xor_sync(0xFFFFFFFF, suA, 1);
        suA += __shfl_xor_sync(0xFFFFFFFF, suA, 2);
        suB += __shfl_xor_sync(0xFFFFFFFF, suB, 1);
        suB += __shfl_xor_sync(0xFFFFFFFF, suB, 2);
        lA = lA * alA + suA;
        lB = lB * alB + suB;

        // rescale O
        #pragma unroll
        for (int jn = 0; jn < 8; jn++) {
            oacc[jn][0] *= alA; oacc[jn][1] *= alA;
            oacc[jn][2] *= alB; oacc[jn][3] *= alB;
        }

        // O += P @ V (fp16 single), 8 k-steps of 16
        #pragma unroll
        for (int k2 = 0; k2 < 8; k2++) {
            uint32_t pa[4];
            pa[0] = pack_f16(sacc[2*k2][0],   sacc[2*k2][1]);
            pa[1] = pack_f16(sacc[2*k2][2],   sacc[2*k2][3]);
            pa[2] = pack_f16(sacc[2*k2+1][0], sacc[2*k2+1][1]);
            pa[3] = pack_f16(sacc[2*k2+1][2], sacc[2*k2+1][3]);
            uint32_t vRowOff = (uint32_t)(k2 * 16 + vKr) * RSTR;
            #pragma unroll
            for (int jp = 0; jp < 4; jp++) {
                uint32_t vh4[4];
                ldsm4t(vh4, sb + FL_V + vRowOff + vCb + jp * 32);
                mma_f16(oacc[jp*2],   pa, &vh4[0]);
                mma_f16(oacc[jp*2+1], pa, &vh4[2]);
            }
        }
    }

    // epilogue: normalize + fp16 store (for Wo GEMM)
    float invA = 1.f / lA, invB = 1.f / lB;
    #pragma unroll
    for (int jn = 0; jn < 8; jn++) {
        int col = h * DH + jn * 8 + qd * 2;
        size_t oA = ((size_t)b * SS + sA) * DD + col;
        size_t oB = ((size_t)b * SS + sB) * DD + col;
        *(__half2*)(Of + oA) = __floats2half2_rn(oacc[jn][0] * invA, oacc[jn][1] * invA);
        *(__half2*)(Of + oB) = __floats2half2_rn(oacc[jn][2] * invB, oacc[jn][3] * invB);
    }
}

// ---------------- launch ----------------------------------------------------
extern "C" void kernel_launch(void* const* d_in, const int* in_sizes, int n_in,
                              void* d_out, int out_size)
{
    (void)in_sizes; (void)n_in; (void)out_size;
    const float* x   = (const float*)d_in[0];
    const float* Wq  = (const float*)d_in[1];
    const float* bq  = (const float*)d_in[2];
    const float* Wk  = (const float*)d_in[3];
    const float* bk  = (const float*)d_in[4];
    const float* Wv  = (const float*)d_in[5];
    const float* bv  = (const float*)d_in[6];
    const float* Wo  = (const float*)d_in[7];
    const float* bo  = (const float*)d_in[8];
    const float* Er  = (const float*)d_in[9];
    const float* W1  = (const float*)d_in[10];
    const float* b1  = (const float*)d_in[11];
    const float* W2  = (const float*)d_in[12];
    const float* b2  = (const float*)d_in[13];
    const float* g1  = (const float*)d_in[14];
    const float* be1 = (const float*)d_in[15];
    const float* g2  = (const float*)d_in[16];
    const float* be2 = (const float*)d_in[17];
    float* y = (float*)d_out;

    float *px1, *px2, *px3;
    __half *prel;
    cudaGetSymbolAddress((void**)&px1,  g_x1);
    cudaGetSymbolAddress((void**)&prel, g_rel);
    cudaGetSymbolAddress((void**)&px2,  g_x2);
    cudaGetSymbolAddress((void**)&px3,  g_x3);

    __half *x1f,*x3f,*avf,*h1f;
    __half *qf,*kf,*vf,*erf,*wq,*wk,*wv,*wo,*w1,*w2;
    cudaGetSymbolAddress((void**)&x1f, g_x1f);
    cudaGetSymbolAddress((void**)&x3f, g_x3f);
    cudaGetSymbolAddress((void**)&qf,  g_qf);
    cudaGetSymbolAddress((void**)&kf,  g_kf);
    cudaGetSymbolAddress((void**)&vf,  g_vf);
    cudaGetSymbolAddress((void**)&avf, g_avf);
    cudaGetSymbolAddress((void**)&h1f, g_h1f);
    cudaGetSymbolAddress((void**)&erf, g_erf);
    cudaGetSymbolAddress((void**)&wq, g_wq); cudaGetSymbolAddress((void**)&wk, g_wk);
    cudaGetSymbolAddress((void**)&wv, g_wv); cudaGetSymbolAddress((void**)&wo, g_wo);
    cudaGetSymbolAddress((void**)&w1, g_w1); cudaGetSymbolAddress((void**)&w2, g_w2);

    cudaFuncSetAttribute(gemm_mma<0,false,true>,  cudaFuncAttributeMaxDynamicSharedMemorySize, GEMM_SMEM);
    cudaFuncSetAttribute(gemm_mma<2,true,false>,  cudaFuncAttributeMaxDynamicSharedMemorySize, GEMM_SMEM);
    cudaFuncSetAttribute(qkv_mma, cudaFuncAttributeMaxDynamicSharedMemorySize, GEMM_SMEM);
    cudaFuncSetAttribute(rel_mma,   cudaFuncAttributeMaxDynamicSharedMemorySize, REL_SMEM);
    cudaFuncSetAttribute(flash_mma, cudaFuncAttributeMaxDynamicSharedMemorySize, FL_SMEM);

    // weight transpose + fp16 convert (4 DxD batched, 2 big separate)
    convBT4<<<dim3(DD/32, DD/32, 4), 256>>>(Wq, Wk, Wv, Wo, wq, wk, wv, wo, DD, DD);
    convBTf<<<dim3(FF/32, DD/32), 256>>>(W1, w1, DD, FF);
    convBTf<<<dim3(DD/32, FF/32), 256>>>(W2, w2, FF, DD);
    convEf<<<(SS*DH + 1023)/1024, 256>>>(Er, erf, SS*DH);

    // x1 = LN(x)
    ln_kernel<<<MM, 256>>>(x, g1, be1, px1, x1f);
    // q/k/v fused (z selects), synchronous staging body
    qkv_mma<<<dim3(DD/128, MM/128, 3), 256, GEMM_SMEM>>>(
        x1f, wq, wk, wv, bq, bk, bv, qf, kf, vf);
    // rel = q@Er^T (band tiles, fp16)
    rel_mma<<<dim3(SS/128, SS/128, BB*HH), 256, REL_SMEM>>>(qf, erf, prel);
    // fused attention
    flash_mma<<<dim3(SS/64, BB*HH), 128, FL_SMEM>>>(qf, kf, vf, prel, avf);
    // x2 = x1 + av@Wo + bo
    gemm_mma<0,false,true><<<dim3(DD/128, MM/128), 256, GEMM_SMEM>>>(
        avf, wo, bo, px1, px2, nullptr, DD, DD, 1.f);
    // x3 = LN(x2)
    ln_kernel<<<MM, 256>>>(px2, g2, be2, px3, x3f);
    // h1 = relu(x3@W1+b1) -> fp16
    gemm_mma<2,true,false><<<dim3(FF/128, MM/128), 256, GEMM_SMEM>>>(
        x3f, w1, b1, nullptr, nullptr, h1f, FF, DD, 1.f);
    // y = x3 + h1@W2 + b2
    gemm_mma<0,false,true><<<dim3(DD/128, MM/128), 256, GEMM_SMEM>>>(
        h1f, w2, b2, px3, y, nullptr, DD, FF, 1.f);
}

// round 17
// speedup vs baseline: 1.2024x; 1.0118x over previous
#include <cuda_runtime.h>
#include <cuda_fp16.h>
#include <math.h>
#include <stdint.h>

#define BB 2
#define SS 2048
#define DD 1024
#define HH 16
#define DH 64
#define FF 4096
#define MM (BB*SS)   // 4096 rows

// ---------------- scratch (device globals; no allocation allowed) ----------
__device__ float  g_x1 [MM*DD];
__device__ __half g_rel[(size_t)BB*HH*SS*SS];   // q@Er^T band, fp16
__device__ float  g_x2 [MM*DD];
__device__ float  g_x3 [MM*DD];

__device__ __half g_x1f[MM*DD];
__device__ __half g_x3f[MM*DD];
__device__ __half g_qf [MM*DD];
__device__ __half g_kf [MM*DD];
__device__ __half g_vf [MM*DD];
__device__ __half g_avf[MM*DD];
__device__ __half g_h1f[(size_t)MM*FF];
__device__ __half g_erf[SS*DH];
__device__ __half g_wq[DD*DD], g_wk[DD*DD], g_wv[DD*DD], g_wo[DD*DD];
__device__ __half g_w1[(size_t)DD*FF], g_w2[(size_t)DD*FF];

// ======================= helpers ============================================
__device__ __forceinline__ uint32_t smem_u32(const void* p) {
    uint32_t a;
    asm("{ .reg .u64 t; cvta.to.shared.u64 t, %1; cvt.u32.u64 %0, t; }"
        : "=r"(a) : "l"(p));
    return a;
}
__device__ __forceinline__ void ldsm4(uint32_t* r, uint32_t addr) {
    asm volatile("ldmatrix.sync.aligned.m8n8.x4.shared.b16 {%0,%1,%2,%3}, [%4];"
        : "=r"(r[0]), "=r"(r[1]), "=r"(r[2]), "=r"(r[3]) : "r"(addr));
}
__device__ __forceinline__ void ldsm4t(uint32_t* r, uint32_t addr) {
    asm volatile("ldmatrix.sync.aligned.m8n8.x4.trans.shared.b16 {%0,%1,%2,%3}, [%4];"
        : "=r"(r[0]), "=r"(r[1]), "=r"(r[2]), "=r"(r[3]) : "r"(addr));
}
__device__ __forceinline__ void mma_f16(float* c, const uint32_t* a, const uint32_t* b) {
    asm volatile("mma.sync.aligned.m16n8k16.row.col.f32.f16.f16.f32 "
        "{%0,%1,%2,%3}, {%4,%5,%6,%7}, {%8,%9}, {%0,%1,%2,%3};"
        : "+f"(c[0]), "+f"(c[1]), "+f"(c[2]), "+f"(c[3])
        : "r"(a[0]), "r"(a[1]), "r"(a[2]), "r"(a[3]), "r"(b[0]), "r"(b[1]));
}
__device__ __forceinline__ uint32_t pack_f16(float x, float y) {
    __half2 h = __floats2half2_rn(x, y);
    return *(uint32_t*)&h;
}

#define RSTR 144
#define ASZ (128 * RSTR)          // 18432 B per 128x64 16-bit array
#define QSZ (64 * RSTR)           // 9216 B per 64x64 16-bit array

// ================== weight transpose + fp16: [K][N] -> [N][K] ===============
__global__ __launch_bounds__(256) void convBT4(
    const float* __restrict__ W0, const float* __restrict__ W1x,
    const float* __restrict__ W2x, const float* __restrict__ W3,
    __half* __restrict__ T0, __half* __restrict__ T1,
    __half* __restrict__ T2, __half* __restrict__ T3, int K, int N)
{
    const float* W = (blockIdx.z == 0) ? W0 : (blockIdx.z == 1) ? W1x
                   : (blockIdx.z == 2) ? W2x : W3;
    __half* T = (blockIdx.z == 0) ? T0 : (blockIdx.z == 1) ? T1
              : (blockIdx.z == 2) ? T2 : T3;
    __shared__ float ts[32][33];
    int n0 = blockIdx.x * 32, k0 = blockIdx.y * 32;
    int tx = threadIdx.x & 31, ty = threadIdx.x >> 5;
    #pragma unroll
    for (int i = 0; i < 4; i++)
        ts[ty + 8*i][tx] = W[(size_t)(k0 + ty + 8*i) * N + n0 + tx];
    __syncthreads();
    #pragma unroll
    for (int i = 0; i < 4; i++) {
        int n = ty + 8*i;
        T[(size_t)(n0 + n) * K + k0 + tx] = __float2half_rn(ts[tx][n]);
    }
}

// W1 (DD x FF) and W2 (FF x DD) in one launch: z selects, roles of bx/by swap
__global__ __launch_bounds__(256) void convBT2big(
    const float* __restrict__ W1s, const float* __restrict__ W2s,
    __half* __restrict__ T1s, __half* __restrict__ T2s)
{
    const float* W; __half* T; int K, N, n0, k0;
    if (blockIdx.z == 0) {         // W1: K=DD, N=FF; grid (FF/32, DD/32)
        W = W1s; T = T1s; K = DD; N = FF;
        n0 = blockIdx.x * 32; k0 = blockIdx.y * 32;
    } else {                        // W2: K=FF, N=DD; swap block roles
        W = W2s; T = T2s; K = FF; N = DD;
        n0 = blockIdx.y * 32; k0 = blockIdx.x * 32;
    }
    __shared__ float ts[32][33];
    int tx = threadIdx.x & 31, ty = threadIdx.x >> 5;
    #pragma unroll
    for (int i = 0; i < 4; i++)
        ts[ty + 8*i][tx] = W[(size_t)(k0 + ty + 8*i) * N + n0 + tx];
    __syncthreads();
    #pragma unroll
    for (int i = 0; i < 4; i++) {
        int n = ty + 8*i;
        T[(size_t)(n0 + n) * K + k0 + tx] = __float2half_rn(ts[tx][n]);
    }
}

// -------- elementwise f16 convert (Er) ---------------------------------------
__global__ __launch_bounds__(256) void convEf(
    const float* __restrict__ X, __half* __restrict__ Xf, int n)
{
    int i = blockIdx.x * 1024 + threadIdx.x * 4;
    if (i >= n) return;
    float4 v = *(const float4*)(X + i);
    *(__half2*)(Xf + i)     = __floats2half2_rn(v.x, v.y);
    *(__half2*)(Xf + i + 2) = __floats2half2_rn(v.z, v.w);
}

// ---------------- LayerNorm: fp32 out + fp16 out ----------------------------
__global__ __launch_bounds__(256) void ln_kernel(
    const float* __restrict__ X, const float* __restrict__ g,
    const float* __restrict__ be, float* __restrict__ Y,
    __half* __restrict__ Yf)
{
    int row = blockIdx.x;
    size_t base = (size_t)row * DD;
    int tid = threadIdx.x;
    float4 v = *(const float4*)(X + base + tid * 4);
    float s = v.x + v.y + v.z + v.w;
    float q = v.x*v.x + v.y*v.y + v.z*v.z + v.w*v.w;

    __shared__ float rs[32], rq[32];
    #pragma unroll
    for (int o = 16; o > 0; o >>= 1) {
        s += __shfl_xor_sync(0xFFFFFFFF, s, o);
        q += __shfl_xor_sync(0xFFFFFFFF, q, o);
    }
    int lane = tid & 31, w = tid >> 5;
    if (lane == 0) { rs[w] = s; rq[w] = q; }
    __syncthreads();
    if (w == 0) {
        s = (lane < 8) ? rs[lane] : 0.f;
        q = (lane < 8) ? rq[lane] : 0.f;
        #pragma unroll
        for (int o = 4; o > 0; o >>= 1) {
            s += __shfl_xor_sync(0xFFFFFFFF, s, o);
            q += __shfl_xor_sync(0xFFFFFFFF, q, o);
        }
        if (lane == 0) { rs[0] = s; rq[0] = q; }
    }
    __syncthreads();
    float mean = rs[0] * (1.f / DD);
    float var  = rq[0] * (1.f / DD) - mean * mean;
    float rstd = rsqrtf(var + 1e-5f);

    float4 gv = *(const float4*)(g  + tid * 4);
    float4 bv = *(const float4*)(be + tid * 4);
    float4 o4;
    o4.x = (v.x - mean) * rstd * gv.x + bv.x;
    o4.y = (v.y - mean) * rstd * gv.y + bv.y;
    o4.z = (v.z - mean) * rstd * gv.z + bv.z;
    o4.w = (v.w - mean) * rstd * gv.w + bv.w;
    *(float4*)(Y + base + tid * 4) = o4;
    *(__half2*)(Yf + base + tid*4)     = __floats2half2_rn(o4.x, o4.y);
    *(__half2*)(Yf + base + tid*4 + 2) = __floats2half2_rn(o4.z, o4.w);
}

// ====== mma.sync fp16 GEMM: C = epi(A@B^T + bias), sync staging =============
#define SA 0
#define SB ASZ
#define GEMM_SMEM (2*ASZ)         // 36864 B

template<int OUTM, bool RELU, bool RES>
__device__ __forceinline__ void gemm_body(
    char* smem, uint32_t sb,
    const __half* __restrict__ Am, const __half* __restrict__ Bm,
    const float* __restrict__ bias, const float* __restrict__ res,
    float* __restrict__ Cf, __half* __restrict__ Cs,
    int N, int K, float scale, int m0, int n0)
{
    int tid = threadIdx.x;
    int lane = tid & 31, wid = tid >> 5;
    int wm = wid & 3, wn = wid >> 2;

    int aRow = wm * 32 + ((lane >> 3) & 1) * 8 + (lane & 7);
    uint32_t aOff = (uint32_t)aRow * RSTR + ((lane >> 4) & 1) * 16;
    int bRow = wn * 64 + ((lane >> 4) & 1) * 8 + (lane & 7);
    uint32_t bOff = (uint32_t)bRow * RSTR + ((lane >> 3) & 1) * 16;

    float acc[2][8][4] = {};

    const int chunks = K >> 6;
    for (int c = 0; c < chunks; c++) {
        size_t koff = (size_t)c * 64;
        #pragma unroll
        for (int i = 0; i < 4; i++) {
            int u = tid + i * 256;
            int row = u >> 3, seg = u & 7;
            uint32_t d = (uint32_t)row * RSTR + seg * 16;
            *(uint4*)(smem + SA + d) = *((const uint4*)(Am + (size_t)(m0+row)*K + koff) + seg);
            *(uint4*)(smem + SB + d) = *((const uint4*)(Bm + (size_t)(n0+row)*K + koff) + seg);
        }
        __syncthreads();

        #pragma unroll
        for (int kk = 0; kk < 4; kk++) {
            uint32_t kb = kk * 32;
            uint32_t ah[2][4];
            ldsm4(ah[0], sb + SA + aOff + kb);
            ldsm4(ah[1], sb + SA + aOff + 16*RSTR + kb);
            uint32_t bh[4][4];
            #pragma unroll
            for (int jp = 0; jp < 4; jp++)
                ldsm4(bh[jp], sb + SB + bOff + (uint32_t)jp*16*RSTR + kb);
            #pragma unroll
            for (int im = 0; im < 2; im++)
                #pragma unroll
                for (int jn = 0; jn < 8; jn++)
                    mma_f16(acc[im][jn], ah[im], &bh[jn >> 1][(jn & 1) * 2]);
        }
        __syncthreads();
    }

    int r = lane >> 2, cc = (lane & 3) * 2;
    #pragma unroll
    for (int im = 0; im < 2; im++) {
        int rg0 = m0 + wm * 32 + im * 16 + r;
        #pragma unroll
        for (int jn = 0; jn < 8; jn++) {
            int col = n0 + wn * 64 + jn * 8 + cc;
            float2 bv = *(const float2*)(bias + col);
            float v0 = (acc[im][jn][0] + bv.x) * scale;
            float v1 = (acc[im][jn][1] + bv.y) * scale;
            float v2 = (acc[im][jn][2] + bv.x) * scale;
            float v3 = (acc[im][jn][3] + bv.y) * scale;
            if (RELU) {
                v0 = fmaxf(v0, 0.f); v1 = fmaxf(v1, 0.f);
                v2 = fmaxf(v2, 0.f); v3 = fmaxf(v3, 0.f);
            }
            size_t o0 = (size_t)rg0 * N + col;
            size_t o1 = (size_t)(rg0 + 8) * N + col;
            if (RES) {
                float2 r0 = *(const float2*)(res + o0);
                float2 r1 = *(const float2*)(res + o1);
                v0 += r0.x; v1 += r0.y; v2 += r1.x; v3 += r1.y;
            }
            if (OUTM == 0) {
                *(float2*)(Cf + o0) = make_float2(v0, v1);
                *(float2*)(Cf + o1) = make_float2(v2, v3);
            } else {
                *(__half2*)(Cs + o0) = __floats2half2_rn(v0, v1);
                *(__half2*)(Cs + o1) = __floats2half2_rn(v2, v3);
            }
        }
    }
}

template<int OUTM, bool RELU, bool RES>
__global__ __launch_bounds__(256)
void gemm_mma(
    const __half* __restrict__ Am, const __half* __restrict__ Bm,
    const float* __restrict__ bias, const float* __restrict__ res,
    float* __restrict__ Cf, __half* __restrict__ Cs,
    int N, int K, float scale)
{
    extern __shared__ char smem[];
    gemm_body<OUTM, RELU, RES>(smem, smem_u32(smem), Am, Bm, bias, res,
                               Cf, Cs, N, K, scale,
                               blockIdx.y * 128, blockIdx.x * 128);
}

// fused QKV: blockIdx.z selects weight/bias/output (sync staging body)
__global__ __launch_bounds__(256)
void qkv_mma(
    const __half* __restrict__ X,
    const __half* __restrict__ Wq, const __half* __restrict__ Wk,
    const __half* __restrict__ Wv,
    const float* __restrict__ bq, const float* __restrict__ bk,
    const float* __restrict__ bv,
    __half* __restrict__ Q, __half* __restrict__ Kk, __half* __restrict__ V)
{
    extern __shared__ char smem[];
    int z = blockIdx.z;
    const __half* B = (z == 0) ? Wq : (z == 1) ? Wk : Wv;
    const float* bi = (z == 0) ? bq : (z == 1) ? bk : bv;
    __half* C       = (z == 0) ? Q  : (z == 1) ? Kk : V;
    float scale     = (z == 0) ? 0.125f : 1.f;
    gemm_body<2, false, false>(smem, smem_u32(smem), X, B, bi, nullptr,
                               nullptr, C, DD, DD, scale,
                               blockIdx.y * 128, blockIdx.x * 128);
}

// ========== rel = q @ Er^T, band tiles only, fp16 in/out (K = 64) ===========
// Stores predicated to the read region: col+1 >= SS-1-row (upper-right triangle)
#define REL_SMEM (2*ASZ)

__global__ __launch_bounds__(256)
void rel_mma(
    const __half* __restrict__ Qf, const __half* __restrict__ Ef,
    __half* __restrict__ out)
{
    int m0 = blockIdx.y * 128, n0 = blockIdx.x * 128;
    if (m0 + n0 + 255 < SS - 1) return;   // tile never read by skew gather
    int bh = blockIdx.z;
    int b = bh >> 4, h = bh & 15;

    extern __shared__ char smem[];
    uint32_t sb = smem_u32(smem);
    int tid = threadIdx.x;
    int lane = tid & 31, wid = tid >> 5;
    int wm = wid & 3, wn = wid >> 2;

    const __half* Qp = Qf + ((size_t)b * SS) * DD + h * DH;

    #pragma unroll
    for (int i = 0; i < 4; i++) {
        int u = tid + i * 256;
        int row = u >> 3, seg = u & 7;
        uint32_t d = (uint32_t)row * RSTR + seg * 16;
        *(uint4*)(smem + 0   + d) = *((const uint4*)(Qp + (size_t)(m0+row)*DD) + seg);
        *(uint4*)(smem + ASZ + d) = *((const uint4*)(Ef + (size_t)(n0+row)*DH) + seg);
    }
    __syncthreads();

    int aRow = wm * 32 + ((lane >> 3) & 1) * 8 + (lane & 7);
    uint32_t aOff = (uint32_t)aRow * RSTR + ((lane >> 4) & 1) * 16;
    int bRow = wn * 64 + ((lane >> 4) & 1) * 8 + (lane & 7);
    uint32_t bOff = (uint32_t)bRow * RSTR + ((lane >> 3) & 1) * 16;

    float acc[2][8][4] = {};
    #pragma unroll
    for (int kk = 0; kk < 4; kk++) {
        uint32_t kb = kk * 32;
        uint32_t ah[2][4];
        ldsm4(ah[0], sb + 0 + aOff + kb);
        ldsm4(ah[1], sb + 0 + aOff + 16*RSTR + kb);
        uint32_t bhf[4][4];
        #pragma unroll
        for (int jp = 0; jp < 4; jp++)
            ldsm4(bhf[jp], sb + ASZ + bOff + (uint32_t)jp*16*RSTR + kb);
        #pragma unroll
        for (int im = 0; im < 2; im++)
            #pragma unroll
            for (int jn = 0; jn < 8; jn++)
                mma_f16(acc[im][jn], ah[im], &bhf[jn >> 1][(jn & 1) * 2]);
    }

    __half* ob = out + (size_t)bh * SS * SS;
    int r = lane >> 2, cc = (lane & 3) * 2;
    #pragma unroll
    for (int im = 0; im < 2; im++) {
        int rg0 = m0 + wm * 32 + im * 16 + r;
        #pragma unroll
        for (int jn = 0; jn < 8; jn++) {
            int col = n0 + wn * 64 + jn * 8 + cc;
            // flash reads only col >= SS-1-row; skip dead stores
            if (col + 1 >= SS - 1 - rg0)
                *(__half2*)(ob + (size_t)rg0 * SS + col) =
                    __floats2half2_rn(acc[im][jn][0], acc[im][jn][1]);
            if (col + 1 >= SS - 1 - (rg0 + 8))
                *(__half2*)(ob + (size_t)(rg0+8) * SS + col) =
                    __floats2half2_rn(acc[im][jn][2], acc[im][jn][3]);
        }
    }
}

// ========== flash attention, fp16 single-product ============================
// CTA: one (b,h) and 64 q-rows, 128 threads (4 warps x 16 rows).
#define FL_Q  0
#define FL_K  QSZ
#define FL_V  (QSZ + ASZ)
#define FL_SMEM (QSZ + 2*ASZ)    // 46080 B

__global__ __launch_bounds__(128)
void flash_mma(
    const __half* __restrict__ Qf, const __half* __restrict__ Kf,
    const __half* __restrict__ Vf, const __half* __restrict__ REL,
    __half* __restrict__ Of)
{
    extern __shared__ char smem[];
    uint32_t sb = smem_u32(smem);
    int tid = threadIdx.x;
    int lane = tid & 31, w = tid >> 5;     // 4 warps
    int s0 = blockIdx.x * 64;
    int bh = blockIdx.y;
    int b = bh >> 4, h = bh & 15;

    const __half* qb = Qf + ((size_t)b * SS) * DD + h * DH;
    const __half* kb = Kf + ((size_t)b * SS) * DD + h * DH;
    const __half* vb = Vf + ((size_t)b * SS) * DD + h * DH;

    // stage Q (64 rows, persistent in smem)
    #pragma unroll
    for (int i = 0; i < 4; i++) {
        int u = tid + i * 128;
        int row = u >> 3, seg = u & 7;
        uint32_t d = (uint32_t)row * RSTR + seg * 16;
        *(uint4*)(smem + FL_Q + d) = *((const uint4*)(qb + (size_t)(s0+row)*DD) + seg);
    }

    int g = lane >> 2, qd = lane & 3;
    int sA = s0 + w * 16 + g;
    int sB = sA + 8;
    const __half* rpA = REL + ((size_t)bh * SS + sA) * SS + (SS - 1 - sA);
    const __half* rpB = REL + ((size_t)bh * SS + sB) * SS + (SS - 1 - sB);

    uint32_t aOff = (uint32_t)(w*16 + ((lane>>3)&1)*8 + (lane&7)) * RSTR + ((lane>>4)&1)*16;
    uint32_t bOff = (uint32_t)(((lane>>4)&1)*8 + (lane&7)) * RSTR + ((lane>>3)&1)*16;
    uint32_t vKr = ((lane>>3)&1)*8 + (lane&7);
    uint32_t vCb = ((lane>>4)&1)*16;

    const float L2E = 1.44269504f;

    float oacc[8][4] = {};
    float mA = -1e30f, mB = -1e30f, lA = 0.f, lB = 0.f;

    for (int c = 0; c < SS/128; c++) {
        int t0 = c * 128;
        __syncthreads();    // protect K/V smem reuse (and Q store on c==0)
        #pragma unroll
        for (int i = 0; i < 8; i++) {
            int u = tid + i * 128;
            int row = u >> 3, seg = u & 7;
            uint32_t d = (uint32_t)row * RSTR + seg * 16;
            *(uint4*)(smem + FL_K + d) = *((const uint4*)(kb + (size_t)(t0+row)*DD) + seg);
            *(uint4*)(smem + FL_V + d) = *((const uint4*)(vb + (size_t)(t0+row)*DD) + seg);
        }
        __syncthreads();

        // S = q @ k^T (fp16 single), 16 n-tiles of 8 cols
        float sacc[16][4] = {};
        #pragma unroll
        for (int kk = 0; kk < 4; kk++) {
            uint32_t kbo = kk * 32;
            uint32_t ah[4];
            ldsm4(ah, sb + FL_Q + aOff + kbo);
            #pragma unroll
            for (int jp = 0; jp < 8; jp++) {
                uint32_t bhf[4];
                ldsm4(bhf, sb + FL_K + bOff + (uint32_t)jp*16*RSTR + kbo);
                mma_f16(sacc[jp*2],   ah, &bhf[0]);
                mma_f16(sacc[jp*2+1], ah, &bhf[2]);
            }
        }

        // skew add (fp16 rel): sacc[jn][0,1] row sA, [2,3] row sB
        if (t0 <= sA) {
            #pragma unroll
            for (int jn = 0; jn < 16; jn++) {
                int t = t0 + jn * 8 + qd * 2;
                if (t     <= sA) sacc[jn][0] += __half2float(__ldg(rpA + t));
                if (t + 1 <= sA) sacc[jn][1] += __half2float(__ldg(rpA + t + 1));
            }
        }
        if (t0 <= sB) {
            #pragma unroll
            for (int jn = 0; jn < 16; jn++) {
                int t = t0 + jn * 8 + qd * 2;
                if (t     <= sB) sacc[jn][2] += __half2float(__ldg(rpB + t));
                if (t + 1 <= sB) sacc[jn][3] += __half2float(__ldg(rpB + t + 1));
            }
        }

        // online softmax (exp2-based, in-place on sacc)
        float cmA = -1e30f, cmB = -1e30f;
        #pragma unroll
        for (int jn = 0; jn < 16; jn++) {
            cmA = fmaxf(cmA, fmaxf(sacc[jn][0], sacc[jn][1]));
            cmB = fmaxf(cmB, fmaxf(sacc[jn][2], sacc[jn][3]));
        }
        cmA = fmaxf(cmA, __shfl_xor_sync(0xFFFFFFFF, cmA, 1));
        cmA = fmaxf(cmA, __shfl_xor_sync(0xFFFFFFFF, cmA, 2));
        cmB = fmaxf(cmB, __shfl_xor_sync(0xFFFFFFFF, cmB, 1));
        cmB = fmaxf(cmB, __shfl_xor_sync(0xFFFFFFFF, cmB, 2));
        float mnA = fmaxf(mA, cmA), mnB = fmaxf(mB, cmB);
        float bA = mnA * L2E, bB = mnB * L2E;
        float alA = exp2f(mA * L2E - bA), alB = exp2f(mB * L2E - bB);
        mA = mnA; mB = mnB;

        float suA = 0.f, suB = 0.f;
        #pragma unroll
        for (int jn = 0; jn < 16; jn++) {
            sacc[jn][0] = exp2f(fmaf(sacc[jn][0], L2E, -bA));
            sacc[jn][1] = exp2f(fmaf(sacc[jn][1], L2E, -bA));
            sacc[jn][2] = exp2f(fmaf(sacc[jn][2], L2E, -bB));
            sacc[jn][3] = exp2f(fmaf(sacc[jn][3], L2E, -bB));
            suA += sacc[jn][0] + sacc[jn][1];
            suB += sacc[jn][2] + sacc[jn][3];
        }
        suA += __shfl_xor_sync(0xFFFFFFFF, suA, 1);
        suA += __shfl_xor_sync(0xFFFFFFFF, suA, 2);
        suB += __shfl_xor_sync(0xFFFFFFFF, suB, 1);
        suB += __shfl_xor_sync(0xFFFFFFFF, suB, 2);
        lA = lA * alA + suA;
        lB = lB * alB + suB;

        // rescale O
        #pragma unroll
        for (int jn = 0; jn < 8; jn++) {
            oacc[jn][0] *= alA; oacc[jn][1] *= alA;
            oacc[jn][2] *= alB; oacc[jn][3] *= alB;
        }

        // O += P @ V (fp16 single), 8 k-steps of 16
        #pragma unroll
        for (int k2 = 0; k2 < 8; k2++) {
            uint32_t pa[4];
            pa[0] = pack_f16(sacc[2*k2][0],   sacc[2*k2][1]);
            pa[1] = pack_f16(sacc[2*k2][2],   sacc[2*k2][3]);
            pa[2] = pack_f16(sacc[2*k2+1][0], sacc[2*k2+1][1]);
            pa[3] = pack_f16(sacc[2*k2+1][2], sacc[2*k2+1][3]);
            uint32_t vRowOff = (uint32_t)(k2 * 16 + vKr) * RSTR;
            #pragma unroll
            for (int jp = 0; jp < 4; jp++) {
                uint32_t vh4[4];
                ldsm4t(vh4, sb + FL_V + vRowOff + vCb + jp * 32);
                mma_f16(oacc[jp*2],   pa, &vh4[0]);
                mma_f16(oacc[jp*2+1], pa, &vh4[2]);
            }
        }
    }

    // epilogue: normalize + fp16 store (for Wo GEMM)
    float invA = 1.f / lA, invB = 1.f / lB;
    #pragma unroll
    for (int jn = 0; jn < 8; jn++) {
        int col = h * DH + jn * 8 + qd * 2;
        size_t oA = ((size_t)b * SS + sA) * DD + col;
        size_t oB = ((size_t)b * SS + sB) * DD + col;
        *(__half2*)(Of + oA) = __floats2half2_rn(oacc[jn][0] * invA, oacc[jn][1] * invA);
        *(__half2*)(Of + oB) = __floats2half2_rn(oacc[jn][2] * invB, oacc[jn][3] * invB);
    }
}

// ---------------- launch ----------------------------------------------------
extern "C" void kernel_launch(void* const* d_in, const int* in_sizes, int n_in,
                              void* d_out, int out_size)
{
    (void)in_sizes; (void)n_in; (void)out_size;
    const float* x   = (const float*)d_in[0];
    const float* Wq  = (const float*)d_in[1];
    const float* bq  = (const float*)d_in[2];
    const float* Wk  = (const float*)d_in[3];
    const float* bk  = (const float*)d_in[4];
    const float* Wv  = (const float*)d_in[5];
    const float* bv  = (const float*)d_in[6];
    const float* Wo  = (const float*)d_in[7];
    const float* bo  = (const float*)d_in[8];
    const float* Er  = (const float*)d_in[9];
    const float* W1  = (const float*)d_in[10];
    const float* b1  = (const float*)d_in[11];
    const float* W2  = (const float*)d_in[12];
    const float* b2  = (const float*)d_in[13];
    const float* g1  = (const float*)d_in[14];
    const float* be1 = (const float*)d_in[15];
    const float* g2  = (const float*)d_in[16];
    const float* be2 = (const float*)d_in[17];
    float* y = (float*)d_out;

    float *px1, *px2, *px3;
    __half *prel;
    cudaGetSymbolAddress((void**)&px1,  g_x1);
    cudaGetSymbolAddress((void**)&prel, g_rel);
    cudaGetSymbolAddress((void**)&px2,  g_x2);
    cudaGetSymbolAddress((void**)&px3,  g_x3);

    __half *x1f,*x3f,*avf,*h1f;
    __half *qf,*kf,*vf,*erf,*wq,*wk,*wv,*wo,*w1,*w2;
    cudaGetSymbolAddress((void**)&x1f, g_x1f);
    cudaGetSymbolAddress((void**)&x3f, g_x3f);
    cudaGetSymbolAddress((void**)&qf,  g_qf);
    cudaGetSymbolAddress((void**)&kf,  g_kf);
    cudaGetSymbolAddress((void**)&vf,  g_vf);
    cudaGetSymbolAddress((void**)&avf, g_avf);
    cudaGetSymbolAddress((void**)&h1f, g_h1f);
    cudaGetSymbolAddress((void**)&erf, g_erf);
    cudaGetSymbolAddress((void**)&wq, g_wq); cudaGetSymbolAddress((void**)&wk, g_wk);
    cudaGetSymbolAddress((void**)&wv, g_wv); cudaGetSymbolAddress((void**)&wo, g_wo);
    cudaGetSymbolAddress((void**)&w1, g_w1); cudaGetSymbolAddress((void**)&w2, g_w2);

    cudaFuncSetAttribute(gemm_mma<0,false,true>,  cudaFuncAttributeMaxDynamicSharedMemorySize, GEMM_SMEM);
    cudaFuncSetAttribute(gemm_mma<2,true,false>,  cudaFuncAttributeMaxDynamicSharedMemorySize, GEMM_SMEM);
    cudaFuncSetAttribute(qkv_mma, cudaFuncAttributeMaxDynamicSharedMemorySize, GEMM_SMEM);
    cudaFuncSetAttribute(rel_mma,   cudaFuncAttributeMaxDynamicSharedMemorySize, REL_SMEM);
    cudaFuncSetAttribute(flash_mma, cudaFuncAttributeMaxDynamicSharedMemorySize, FL_SMEM);

    // weight transpose + fp16 convert (4 DxD batched; W1+W2 batched)
    convBT4<<<dim3(DD/32, DD/32, 4), 256>>>(Wq, Wk, Wv, Wo, wq, wk, wv, wo, DD, DD);
    convBT2big<<<dim3(FF/32, DD/32, 2), 256>>>(W1, W2, w1, w2);
    convEf<<<(SS*DH + 1023)/1024, 256>>>(Er, erf, SS*DH);

    // x1 = LN(x)
    ln_kernel<<<MM, 256>>>(x, g1, be1, px1, x1f);
    // q/k/v fused (z selects), synchronous staging body
    qkv_mma<<<dim3(DD/128, MM/128, 3), 256, GEMM_SMEM>>>(
        x1f, wq, wk, wv, bq, bk, bv, qf, kf, vf);
    // rel = q@Er^T (band tiles, fp16, stores predicated to read region)
    rel_mma<<<dim3(SS/128, SS/128, BB*HH), 256, REL_SMEM>>>(qf, erf, prel);
    // fused attention
    flash_mma<<<dim3(SS/64, BB*HH), 128, FL_SMEM>>>(qf, kf, vf, prel, avf);
    // x2 = x1 + av@Wo + bo
    gemm_mma<0,false,true><<<dim3(DD/128, MM/128), 256, GEMM_SMEM>>>(
        avf, wo, bo, px1, px2, nullptr, DD, DD, 1.f);
    // x3 = LN(x2)
    ln_kernel<<<MM, 256>>>(px2, g2, be2, px3, x3f);
    // h1 = relu(x3@W1+b1) -> fp16
    gemm_mma<2,true,false><<<dim3(FF/128, MM/128), 256, GEMM_SMEM>>>(
        x3f, w1, b1, nullptr, nullptr, h1f, FF, DD, 1.f);
    // y = x3 + h1@W2 + b2
    gemm_mma<0,false,true><<<dim3(DD/128, MM/128), 256, GEMM_SMEM>>>(
        h1f, w2, b2, px3, y, nullptr, DD, FF, 1.f);
}